// round 16
// baseline (speedup 1.0000x reference)
#include <cuda_runtime.h>
#include <cstdint>
#include <cstddef>

// Problem constants
#define BB   32
#define TT   2048
#define HH   256
#define OBS  64
#define EMB  128
#define G4   1024   // 4*H

// ---------------- device scratch (no allocations allowed) ----------------
__device__ float g_xz[(size_t)BB * TT * G4];   // 256 MB: x-path preactivations
__device__ float g_Wc[OBS * G4];               // W_embed @ kernel
__device__ float g_bc[G4];                     // b_embed @ kernel + bias

// ---------------- packed f32x2 helpers ------------------------------------
__device__ __forceinline__ void ffma2(unsigned long long& d,
                                      unsigned long long a,
                                      unsigned long long b) {
    asm("fma.rn.f32x2 %0, %1, %2, %0;" : "+l"(d) : "l"(a), "l"(b));
}
__device__ __forceinline__ unsigned long long packf2(float lo, float hi) {
    unsigned long long r;
    asm("mov.b64 %0, {%1,%2};" : "=l"(r) : "f"(lo), "f"(hi));
    return r;
}
__device__ __forceinline__ void unpackf2(float& lo, float& hi, unsigned long long a) {
    asm("mov.b64 {%0,%1}, %2;" : "=f"(lo), "=f"(hi) : "l"(a));
}
__device__ __forceinline__ float pairsum(unsigned long long a) {
    float lo, hi;
    asm("mov.b64 {%0,%1}, %2;" : "=f"(lo), "=f"(hi) : "l"(a));
    return lo + hi;
}

// ---------------- kernel 1: fold the two dense layers --------------------
__global__ void prep_kernel(const float* __restrict__ W_embed,
                            const float* __restrict__ b_embed,
                            const float* __restrict__ kern,
                            const float* __restrict__ bias) {
    int j = threadIdx.x;       // 0..1023
    int i = blockIdx.x;        // 0..64 (64 = bc row)
    if (i < OBS) {
        float acc = 0.f;
        #pragma unroll 4
        for (int e = 0; e < EMB; e++)
            acc += W_embed[i * EMB + e] * kern[e * G4 + j];
        g_Wc[i * G4 + j] = acc;
    } else {
        float acc = bias[j];
        #pragma unroll 4
        for (int e = 0; e < EMB; e++)
            acc += b_embed[e] * kern[e * G4 + j];
        g_bc[j] = acc;
    }
}

// ---------------- kernel 2: xz = obs @ Wc + bc (f32x2 packed) --------------
#define K2_ROWS 32
__global__ void __launch_bounds__(256) xz_kernel(const float* __restrict__ obs) {
    __shared__ __align__(16) float obs_s[OBS * K2_ROWS];  // [k][r], r contiguous
    int bid    = blockIdx.x;
    int colBlk = bid & 1;
    int rowBlk = bid >> 1;
    int row0   = rowBlk * K2_ROWS;
    int col0   = colBlk * 512;
    int tid    = threadIdx.x;

    for (int idx = tid; idx < OBS * K2_ROWS; idx += 256) {
        int r = idx >> 6, k = idx & 63;
        obs_s[k * K2_ROWS + r] = obs[(size_t)(row0 + r) * OBS + k];
    }
    __syncthreads();

    int c0 = col0 + tid;
    int c1 = c0 + 256;
    unsigned long long acc0[K2_ROWS / 2], acc1[K2_ROWS / 2];
    #pragma unroll
    for (int r = 0; r < K2_ROWS / 2; r++) { acc0[r] = 0ull; acc1[r] = 0ull; }

    #pragma unroll 2
    for (int k = 0; k < OBS; k++) {
        float w0 = g_Wc[k * G4 + c0];
        float w1 = g_Wc[k * G4 + c1];
        unsigned long long w0p = packf2(w0, w0);
        unsigned long long w1p = packf2(w1, w1);
        const ulonglong2* o2 = (const ulonglong2*)&obs_s[k * K2_ROWS];
        #pragma unroll
        for (int rp = 0; rp < K2_ROWS / 4; rp++) {
            ulonglong2 oo = o2[rp];
            ffma2(acc0[2 * rp],     w0p, oo.x);
            ffma2(acc0[2 * rp + 1], w0p, oo.y);
            ffma2(acc1[2 * rp],     w1p, oo.x);
            ffma2(acc1[2 * rp + 1], w1p, oo.y);
        }
    }
    float b0 = g_bc[c0], b1 = g_bc[c1];
    #pragma unroll
    for (int rp = 0; rp < K2_ROWS / 2; rp++) {
        float lo, hi;
        unpackf2(lo, hi, acc0[rp]);
        size_t rA = (size_t)(row0 + 2 * rp);
        g_xz[rA * G4 + c0]       = lo + b0;
        g_xz[(rA + 1) * G4 + c0] = hi + b0;
        unpackf2(lo, hi, acc1[rp]);
        g_xz[rA * G4 + c1]       = lo + b1;
        g_xz[(rA + 1) * G4 + c1] = hi + b1;
    }
}

// ---------------- kernel 3: masked LSTM recurrence ------------------------
// R15 skeleton: 8 clusters x 8 CTAs; NB=4; 512 threads; broadcast-LDS
// matvec; parity mbarriers; warp-15 poll; st.async.v4 exchange.
// R16 delta: WARP-LOCAL fused epilogue. After the zpart bar, warp w owns
// (batch w&3, unit-group w>>2); lane = u_local*4 + gate. Lane computes one
// gate activation; 3 shuffles gather gates to the g==0 leader; leaders run
// the c-chain + STS hstage; __syncwarp; 16 lanes/warp send 1 chunk each.
// NO third __syncthreads, no act_s. zpart gate blocks padded by 8 floats
// (colp = gate*40 + ul, row 160) so the strided act reads are conflict-free.
#define CLU 8
#define NB  4
#define ZROW 160
#define TXB (NB * 32 * CLU * 4)   // 4096 B received per CTA per step

__device__ __forceinline__ void stasync_v4(uint32_t laddr, uint32_t lmbar,
                                           uint32_t peer, uint4 v) {
    asm volatile(
        "{\n\t.reg .b32 ra, rb;\n\t"
        "mapa.shared::cluster.u32 ra, %0, %1;\n\t"
        "mapa.shared::cluster.u32 rb, %2, %1;\n\t"
        "st.async.shared::cluster.mbarrier::complete_tx::bytes.v4.b32"
        " [ra], {%3,%4,%5,%6}, [rb];\n\t}"
        :: "r"(laddr), "r"(peer), "r"(lmbar),
           "r"(v.x), "r"(v.y), "r"(v.z), "r"(v.w) : "memory");
}
__device__ __forceinline__ void mbar_init(uint32_t mbar, uint32_t cnt) {
    asm volatile("mbarrier.init.shared.b64 [%0], %1;" :: "r"(mbar), "r"(cnt) : "memory");
}
__device__ __forceinline__ void mbar_arm(uint32_t mbar, uint32_t tx) {
    asm volatile("mbarrier.arrive.expect_tx.shared.b64 _, [%0], %1;"
                 :: "r"(mbar), "r"(tx) : "memory");
}
__device__ __forceinline__ void mbar_wait(uint32_t mbar, uint32_t parity) {
    uint32_t done;
    asm volatile(
        "{\n\t.reg .pred p;\n\t"
        "mbarrier.try_wait.parity.acquire.cluster.shared::cta.b64 p, [%1], %2;\n\t"
        "selp.b32 %0, 1, 0, p;\n\t}"
        : "=r"(done) : "r"(mbar), "r"(parity) : "memory");
    if (!done) {
        asm volatile(
            "{\n\t.reg .pred P1;\n\t"
            "W_%=:\n\t"
            "mbarrier.try_wait.parity.acquire.cluster.shared::cta.b64 P1, [%0], %1, 0x989680;\n\t"
            "@P1 bra.uni D_%=;\n\t"
            "bra.uni W_%=;\n\t"
            "D_%=:\n\t}"
            :: "r"(mbar), "r"(parity) : "memory");
    }
}
__device__ __forceinline__ void cl_sync() {
    asm volatile("barrier.cluster.arrive.aligned;" ::: "memory");
    asm volatile("barrier.cluster.wait.aligned;" ::: "memory");
}
__device__ __forceinline__ float sigf(float u) {
    return 1.f / (1.f + __expf(-u));
}

__global__ void __launch_bounds__(512, 1) __cluster_dims__(CLU, 1, 1)
rec_kernel(const float* __restrict__ S, const float* __restrict__ M,
           const float* __restrict__ rec, float* __restrict__ out) {
    __shared__ __align__(16) float hbuf[2][NB][HH];    // [parity][batch][k]
    __shared__ __align__(16) float hstage[NB][32];     // [batch][unit]
    __shared__ float zpart[2][NB][4][ZROW];            // padded gate blocks
    __shared__ __align__(8) unsigned long long mbar[2];

    const int tid  = threadIdx.x;
    const int rank = blockIdx.x & (CLU - 1);
    const int cid  = blockIdx.x / CLU;
    const int b0g  = cid * NB;

    // ---- matvec coordinates (R8 verbatim) ----
    const int col  = tid & 127;
    const int kq   = tid >> 7;            // 0..3
    const int gate = col >> 5;
    const int ul   = col & 31;
    const int j    = gate * HH + rank * 32 + ul;   // global gate column
    const int k0   = kq * 64;
    const int colp = gate * 40 + ul;               // padded zpart column

    // ---- epilogue coordinates: warp w = (batch w&3, unit-group w>>2) ----
    const int w    = tid >> 5;
    const int lane = tid & 31;
    const int ab   = w & 3;                        // batch
    const int eg   = lane & 3;                     // this lane's gate
    const int uloc = (w >> 2) * 8 + (lane >> 2);   // CTA-local unit 0..31
    const int aj   = eg * HH + rank * 32 + uloc;   // x column for this lane
    const bool leader = (eg == 0);

    const uint32_t hbase = (uint32_t)__cvta_generic_to_shared(&hbuf[0][0][0]);
    const uint32_t mbase = (uint32_t)__cvta_generic_to_shared(&mbar[0]);

    // R slice -> registers as adjacent-k f32x2 pairs (32 u64 regs)
    unsigned long long R2[32];
    #pragma unroll
    for (int i = 0; i < 32; i++) {
        float r0 = rec[(unsigned)(k0 + 2 * i)     * G4 + j];
        float r1 = rec[(unsigned)(k0 + 2 * i + 1) * G4 + j];
        R2[i] = packf2(r0, r1);
    }

    if (tid == 0) {
        mbar_init(mbase, 1);
        mbar_init(mbase + 8, 1);
        asm volatile("fence.mbarrier_init.release.cluster;" ::: "memory");
        mbar_arm(mbase, TXB);
        mbar_arm(mbase + 8, TXB);
    }

    // Init h (parity 0) and c from S = [h | c]
    for (int idx = tid; idx < NB * HH; idx += 512) {
        int b = idx >> 8, k = idx & 255;
        hbuf[0][b][k] = S[(unsigned)(b0g + b) * (2 * HH) + k];
    }
    // c state lives in leader lanes: (batch ab, unit uloc)
    float c_st = 0.f;
    if (leader)
        c_st = S[(unsigned)(b0g + ab) * (2 * HH) + HH + rank * 32 + uloc];
    __syncthreads();
    cl_sync();   // all peers' mbarriers initialized+armed, hbuf[0] ready

    // Per-lane x/M prefetch for t=0
    const unsigned rowoff = (unsigned)(b0g + ab) * TT;
    float xv = g_xz[(size_t)rowoff * G4 + aj];
    float mv = M[rowoff];

    int ph0 = 0, ph1 = 0;

    for (int t = 0; t < TT; t++) {
        const int p  = t & 1;
        const int pn = p ^ 1;

        if (t > 0) {
            // warp 15 polls; bar releases; re-arm after bar (off wait chain)
            if (tid >= 480) {
                if (p) { mbar_wait(mbase + 8, ph1); }
                else   { mbar_wait(mbase,     ph0); }
            }
            __syncthreads();
            if (tid == 480) mbar_arm(mbase + (p ? 8u : 0u), TXB);
            if (p) ph1 ^= 1; else ph0 ^= 1;
        }

        // ---- matvec (R8 verbatim): broadcast LDS + FFMA2 ----
        const ulonglong2* H0 = (const ulonglong2*)&hbuf[p][0][k0];
        const ulonglong2* H1 = (const ulonglong2*)&hbuf[p][1][k0];
        const ulonglong2* H2 = (const ulonglong2*)&hbuf[p][2][k0];
        const ulonglong2* H3 = (const ulonglong2*)&hbuf[p][3][k0];
        unsigned long long a00 = 0, a01 = 0, a10 = 0, a11 = 0;
        unsigned long long a20 = 0, a21 = 0, a30 = 0, a31 = 0;
        #pragma unroll
        for (int i = 0; i < 16; i++) {
            ulonglong2 h0 = H0[i];
            ulonglong2 h1 = H1[i];
            ulonglong2 h2 = H2[i];
            ulonglong2 h3 = H3[i];
            ffma2(a00, R2[2 * i],     h0.x);
            ffma2(a01, R2[2 * i + 1], h0.y);
            ffma2(a10, R2[2 * i],     h1.x);
            ffma2(a11, R2[2 * i + 1], h1.y);
            ffma2(a20, R2[2 * i],     h2.x);
            ffma2(a21, R2[2 * i + 1], h2.y);
            ffma2(a30, R2[2 * i],     h3.x);
            ffma2(a31, R2[2 * i + 1], h3.y);
        }
        zpart[p][0][kq][colp] = pairsum(a00) + pairsum(a01);
        zpart[p][1][kq][colp] = pairsum(a10) + pairsum(a11);
        zpart[p][2][kq][colp] = pairsum(a20) + pairsum(a21);
        zpart[p][3][kq][colp] = pairsum(a30) + pairsum(a31);
        __syncthreads();

        // latch step-t mask BEFORE the prefetch overwrites mv
        const float mvc = mv;

        // ---- fused warp-local epilogue ----
        {
            const int zc = eg * 40 + uloc;       // padded column
            float z = zpart[p][ab][0][zc] + zpart[p][ab][1][zc]
                    + zpart[p][ab][2][zc] + zpart[p][ab][3][zc];
            const float keep = 1.f - mvc;
            float uval = xv + keep * z;
            float uu   = (eg == 2) ? 2.f * uval : uval;
            float s    = sigf(uu);
            float act  = (eg == 2) ? 2.f * s - 1.f : s;

            // gather the 4 gates to the leader (eg==0) lane
            const int base = lane & ~3;
            float fg = __shfl_sync(0xffffffffu, act, base + 1);
            float gg = __shfl_sync(0xffffffffu, act, base + 2);
            float og = __shfl_sync(0xffffffffu, act, base + 3);

            if (leader) {
                float c = fg * (keep * c_st) + act * gg;
                c_st = c;
                float th = 2.f * sigf(2.f * c) - 1.f;
                float hh = og * th;
                if (t < TT - 1) hstage[ab][uloc] = hh;
                out[(size_t)(rowoff + (unsigned)t) * HH + rank * 32 + uloc] = hh;
            }
        }
        // prefetch next step's x/M (all lanes)
        if (t < TT - 1) {
            xv = g_xz[(size_t)(rowoff + (unsigned)t + 1u) * G4 + aj];
            mv = M[rowoff + (unsigned)t + 1u];
        }
        __syncwarp();

        // sends: warp (ab, ug) owns chunks {2ug, 2ug+1} of batch ab;
        // lane l<16 sends chunk 2ug+(l&1) to peer l>>1. 16 sends/warp.
        if (t < TT - 1 && lane < 16) {
            const int chunk = 2 * (w >> 2) + (lane & 1);
            const uint32_t pr = (uint32_t)(lane >> 1);
            uint4 v = *(const uint4*)&hstage[ab][chunk * 4];
            uint32_t laddr = hbase +
                (uint32_t)(((pn * NB + ab) * HH + rank * 32 + chunk * 4) * 4);
            uint32_t lmb = mbase + (uint32_t)(pn * 8);
            stasync_v4(laddr, lmb, pr, v);
        }
    }
    cl_sync();   // don't exit while peers may still write our smem
}

// ---------------- launch ---------------------------------------------------
extern "C" void kernel_launch(void* const* d_in, const int* in_sizes, int n_in,
                              void* d_out, int out_size) {
    const float* obs     = (const float*)d_in[0];
    const float* S       = (const float*)d_in[1];
    const float* M       = (const float*)d_in[2];
    const float* W_embed = (const float*)d_in[3];
    const float* b_embed = (const float*)d_in[4];
    const float* kern    = (const float*)d_in[5];
    const float* rec     = (const float*)d_in[6];
    const float* bias    = (const float*)d_in[7];
    float* out = (float*)d_out;

    prep_kernel<<<65, 1024>>>(W_embed, b_embed, kern, bias);
    xz_kernel<<<4096, 256>>>(obs);
    rec_kernel<<<BB / NB * CLU, 512>>>(S, M, rec, out);
}

// round 17
// speedup vs baseline: 1.9018x; 1.9018x over previous
#include <cuda_runtime.h>
#include <cstdint>
#include <cstddef>

// Problem constants
#define BB   32
#define TT   2048
#define HH   256
#define OBS  64
#define EMB  128
#define G4   1024   // 4*H

// ---------------- device scratch (no allocations allowed) ----------------
__device__ float g_xz[(size_t)BB * TT * G4];   // 256 MB: x-path preactivations
__device__ float g_Wc[OBS * G4];               // W_embed @ kernel
__device__ float g_bc[G4];                     // b_embed @ kernel + bias

// ---------------- packed f32x2 helpers ------------------------------------
__device__ __forceinline__ void ffma2(unsigned long long& d,
                                      unsigned long long a,
                                      unsigned long long b) {
    asm("fma.rn.f32x2 %0, %1, %2, %0;" : "+l"(d) : "l"(a), "l"(b));
}
__device__ __forceinline__ unsigned long long packf2(float lo, float hi) {
    unsigned long long r;
    asm("mov.b64 %0, {%1,%2};" : "=l"(r) : "f"(lo), "f"(hi));
    return r;
}
__device__ __forceinline__ void unpackf2(float& lo, float& hi, unsigned long long a) {
    asm("mov.b64 {%0,%1}, %2;" : "=f"(lo), "=f"(hi) : "l"(a));
}
__device__ __forceinline__ float pairsum(unsigned long long a) {
    float lo, hi;
    asm("mov.b64 {%0,%1}, %2;" : "=f"(lo), "=f"(hi) : "l"(a));
    return lo + hi;
}

// ---------------- kernel 1: fold the two dense layers --------------------
__global__ void prep_kernel(const float* __restrict__ W_embed,
                            const float* __restrict__ b_embed,
                            const float* __restrict__ kern,
                            const float* __restrict__ bias) {
    int j = threadIdx.x;       // 0..1023
    int i = blockIdx.x;        // 0..64 (64 = bc row)
    if (i < OBS) {
        float acc = 0.f;
        #pragma unroll 4
        for (int e = 0; e < EMB; e++)
            acc += W_embed[i * EMB + e] * kern[e * G4 + j];
        g_Wc[i * G4 + j] = acc;
    } else {
        float acc = bias[j];
        #pragma unroll 4
        for (int e = 0; e < EMB; e++)
            acc += b_embed[e] * kern[e * G4 + j];
        g_bc[j] = acc;
    }
}

// ---------------- kernel 2: xz = obs @ Wc + bc (f32x2 packed) --------------
#define K2_ROWS 32
__global__ void __launch_bounds__(256) xz_kernel(const float* __restrict__ obs) {
    __shared__ __align__(16) float obs_s[OBS * K2_ROWS];  // [k][r], r contiguous
    int bid    = blockIdx.x;
    int colBlk = bid & 1;
    int rowBlk = bid >> 1;
    int row0   = rowBlk * K2_ROWS;
    int col0   = colBlk * 512;
    int tid    = threadIdx.x;

    for (int idx = tid; idx < OBS * K2_ROWS; idx += 256) {
        int r = idx >> 6, k = idx & 63;
        obs_s[k * K2_ROWS + r] = obs[(size_t)(row0 + r) * OBS + k];
    }
    __syncthreads();

    int c0 = col0 + tid;
    int c1 = c0 + 256;
    unsigned long long acc0[K2_ROWS / 2], acc1[K2_ROWS / 2];
    #pragma unroll
    for (int r = 0; r < K2_ROWS / 2; r++) { acc0[r] = 0ull; acc1[r] = 0ull; }

    #pragma unroll 2
    for (int k = 0; k < OBS; k++) {
        float w0 = g_Wc[k * G4 + c0];
        float w1 = g_Wc[k * G4 + c1];
        unsigned long long w0p = packf2(w0, w0);
        unsigned long long w1p = packf2(w1, w1);
        const ulonglong2* o2 = (const ulonglong2*)&obs_s[k * K2_ROWS];
        #pragma unroll
        for (int rp = 0; rp < K2_ROWS / 4; rp++) {
            ulonglong2 oo = o2[rp];
            ffma2(acc0[2 * rp],     w0p, oo.x);
            ffma2(acc0[2 * rp + 1], w0p, oo.y);
            ffma2(acc1[2 * rp],     w1p, oo.x);
            ffma2(acc1[2 * rp + 1], w1p, oo.y);
        }
    }
    float b0 = g_bc[c0], b1 = g_bc[c1];
    #pragma unroll
    for (int rp = 0; rp < K2_ROWS / 2; rp++) {
        float lo, hi;
        unpackf2(lo, hi, acc0[rp]);
        size_t rA = (size_t)(row0 + 2 * rp);
        g_xz[rA * G4 + c0]       = lo + b0;
        g_xz[(rA + 1) * G4 + c0] = hi + b0;
        unpackf2(lo, hi, acc1[rp]);
        g_xz[rA * G4 + c1]       = lo + b1;
        g_xz[(rA + 1) * G4 + c1] = hi + b1;
    }
}

// ---------------- kernel 3: masked LSTM recurrence ------------------------
// R15 skeleton (measured best, frozen): 8 clusters x 8 CTAs; NB=4; 512
// threads; parity mbarriers; warp-15 poll; 16-warp act phase; c-chain +
// sends on warps 0-3 (sends before out STG); st.async.v4 exchange.
// R17 delta (matvec-internal only): each thread owns TWO columns x 32 k
// (kq8 = tid>>6 in 0..7, colA = tid&63, colB = colA+64). Each 16-B h load
// now feeds both columns -> LDS.128 per thread drops 64 -> 32 at equal
// FFMA2 count; zpart becomes [batch][8][128] (8-way K reduce).
#define CLU 8
#define NB  4
#define TXB (NB * 32 * CLU * 4)   // 4096 B received per CTA per step

__device__ __forceinline__ void stasync_v4(uint32_t laddr, uint32_t lmbar,
                                           uint32_t peer, uint4 v) {
    asm volatile(
        "{\n\t.reg .b32 ra, rb;\n\t"
        "mapa.shared::cluster.u32 ra, %0, %1;\n\t"
        "mapa.shared::cluster.u32 rb, %2, %1;\n\t"
        "st.async.shared::cluster.mbarrier::complete_tx::bytes.v4.b32"
        " [ra], {%3,%4,%5,%6}, [rb];\n\t}"
        :: "r"(laddr), "r"(peer), "r"(lmbar),
           "r"(v.x), "r"(v.y), "r"(v.z), "r"(v.w) : "memory");
}
__device__ __forceinline__ void mbar_init(uint32_t mbar, uint32_t cnt) {
    asm volatile("mbarrier.init.shared.b64 [%0], %1;" :: "r"(mbar), "r"(cnt) : "memory");
}
__device__ __forceinline__ void mbar_arm(uint32_t mbar, uint32_t tx) {
    asm volatile("mbarrier.arrive.expect_tx.shared.b64 _, [%0], %1;"
                 :: "r"(mbar), "r"(tx) : "memory");
}
__device__ __forceinline__ void mbar_wait(uint32_t mbar, uint32_t parity) {
    uint32_t done;
    asm volatile(
        "{\n\t.reg .pred p;\n\t"
        "mbarrier.try_wait.parity.acquire.cluster.shared::cta.b64 p, [%1], %2;\n\t"
        "selp.b32 %0, 1, 0, p;\n\t}"
        : "=r"(done) : "r"(mbar), "r"(parity) : "memory");
    if (!done) {
        asm volatile(
            "{\n\t.reg .pred P1;\n\t"
            "W_%=:\n\t"
            "mbarrier.try_wait.parity.acquire.cluster.shared::cta.b64 P1, [%0], %1, 0x989680;\n\t"
            "@P1 bra.uni D_%=;\n\t"
            "bra.uni W_%=;\n\t"
            "D_%=:\n\t}"
            :: "r"(mbar), "r"(parity) : "memory");
    }
}
__device__ __forceinline__ void cl_sync() {
    asm volatile("barrier.cluster.arrive.aligned;" ::: "memory");
    asm volatile("barrier.cluster.wait.aligned;" ::: "memory");
}
__device__ __forceinline__ float sigf(float u) {
    return 1.f / (1.f + __expf(-u));
}

__global__ void __launch_bounds__(512, 1) __cluster_dims__(CLU, 1, 1)
rec_kernel(const float* __restrict__ S, const float* __restrict__ M,
           const float* __restrict__ rec, float* __restrict__ out) {
    __shared__ __align__(16) float hbuf[2][NB][HH];    // [parity][batch][k]
    __shared__ __align__(16) float hstage[NB][32];     // [batch][unit]
    __shared__ float zpart[2][NB][8][128];             // [parity][batch][kq8][col]
    __shared__ float act_s[4][NB][32];                 // [gate][batch][unit]
    __shared__ __align__(8) unsigned long long mbar[2];

    const int tid  = threadIdx.x;
    const int rank = blockIdx.x & (CLU - 1);
    const int cid  = blockIdx.x / CLU;
    const int b0g  = cid * NB;

    // ---- matvec coordinates (2 columns x 32 k per thread) ----
    const int colA = tid & 63;            // column A (0..63)
    const int colB = colA + 64;           // column B (64..127)
    const int kq8  = tid >> 6;            // 0..7
    const int k0   = kq8 * 32;
    const int gA   = colA >> 5, uA = colA & 31;
    const int gB   = colB >> 5, uB = colB & 31;
    const int jA   = gA * HH + rank * 32 + uA;
    const int jB   = gB * HH + rank * 32 + uB;

    // ---- activation-phase coordinates: warp w = (batch, gate) ----
    const int w    = tid >> 5;
    const int lane = tid & 31;
    const int ab   = w & 3;               // batch
    const int ag   = w >> 2;              // gate
    const int aj   = ag * HH + rank * 32 + lane;   // x column for this lane

    const uint32_t hbase = (uint32_t)__cvta_generic_to_shared(&hbuf[0][0][0]);
    const uint32_t mbase = (uint32_t)__cvta_generic_to_shared(&mbar[0]);

    // R slices: 16 f32x2 pairs per column (32 k each), 32 u64 regs total
    unsigned long long R2[32];
    #pragma unroll
    for (int i = 0; i < 16; i++) {
        float r0 = rec[(unsigned)(k0 + 2 * i)     * G4 + jA];
        float r1 = rec[(unsigned)(k0 + 2 * i + 1) * G4 + jA];
        R2[i] = packf2(r0, r1);
    }
    #pragma unroll
    for (int i = 0; i < 16; i++) {
        float r0 = rec[(unsigned)(k0 + 2 * i)     * G4 + jB];
        float r1 = rec[(unsigned)(k0 + 2 * i + 1) * G4 + jB];
        R2[16 + i] = packf2(r0, r1);
    }

    if (tid == 0) {
        mbar_init(mbase, 1);
        mbar_init(mbase + 8, 1);
        asm volatile("fence.mbarrier_init.release.cluster;" ::: "memory");
        mbar_arm(mbase, TXB);
        mbar_arm(mbase + 8, TXB);
    }

    // Init h (parity 0) and c from S = [h | c]
    for (int idx = tid; idx < NB * HH; idx += 512) {
        int b = idx >> 8, k = idx & 255;
        hbuf[0][b][k] = S[(unsigned)(b0g + b) * (2 * HH) + k];
    }
    // c state lives in warps 0-3 (batch = w), lane = unit
    float c_st = 0.f;
    if (w < 4)
        c_st = S[(unsigned)(b0g + w) * (2 * HH) + HH + rank * 32 + lane];
    __syncthreads();
    cl_sync();   // all peers' mbarriers initialized+armed, hbuf[0] ready

    // Per-warp x/M prefetch for t=0: lane covers (batch ab, gate ag, unit lane)
    const unsigned rowoff = (unsigned)(b0g + ab) * TT;
    float xv = g_xz[(size_t)rowoff * G4 + aj];
    float mv = M[rowoff];

    int ph0 = 0, ph1 = 0;

    for (int t = 0; t < TT; t++) {
        const int p  = t & 1;
        const int pn = p ^ 1;

        if (t > 0) {
            // warp 15 polls; bar releases; re-arm after bar (off wait chain)
            if (tid >= 480) {
                if (p) { mbar_wait(mbase + 8, ph1); }
                else   { mbar_wait(mbase,     ph0); }
            }
            __syncthreads();
            if (tid == 480) mbar_arm(mbase + (p ? 8u : 0u), TXB);
            if (p) ph1 ^= 1; else ph0 ^= 1;
        }

        // ---- matvec: broadcast LDS, each 16-B load feeds BOTH columns ----
        const ulonglong2* H0 = (const ulonglong2*)&hbuf[p][0][k0];
        const ulonglong2* H1 = (const ulonglong2*)&hbuf[p][1][k0];
        const ulonglong2* H2 = (const ulonglong2*)&hbuf[p][2][k0];
        const ulonglong2* H3 = (const ulonglong2*)&hbuf[p][3][k0];
        unsigned long long aA0 = 0, aA1 = 0, aA2 = 0, aA3 = 0;
        unsigned long long aB0 = 0, aB1 = 0, aB2 = 0, aB3 = 0;
        #pragma unroll
        for (int i = 0; i < 8; i++) {
            ulonglong2 h0 = H0[i];
            ulonglong2 h1 = H1[i];
            ulonglong2 h2 = H2[i];
            ulonglong2 h3 = H3[i];
            ffma2(aA0, R2[2 * i],      h0.x);
            ffma2(aA0, R2[2 * i + 1],  h0.y);
            ffma2(aB0, R2[16 + 2 * i],     h0.x);
            ffma2(aB0, R2[16 + 2 * i + 1], h0.y);
            ffma2(aA1, R2[2 * i],      h1.x);
            ffma2(aA1, R2[2 * i + 1],  h1.y);
            ffma2(aB1, R2[16 + 2 * i],     h1.x);
            ffma2(aB1, R2[16 + 2 * i + 1], h1.y);
            ffma2(aA2, R2[2 * i],      h2.x);
            ffma2(aA2, R2[2 * i + 1],  h2.y);
            ffma2(aB2, R2[16 + 2 * i],     h2.x);
            ffma2(aB2, R2[16 + 2 * i + 1], h2.y);
            ffma2(aA3, R2[2 * i],      h3.x);
            ffma2(aA3, R2[2 * i + 1],  h3.y);
            ffma2(aB3, R2[16 + 2 * i],     h3.x);
            ffma2(aB3, R2[16 + 2 * i + 1], h3.y);
        }
        zpart[p][0][kq8][colA] = pairsum(aA0);
        zpart[p][1][kq8][colA] = pairsum(aA1);
        zpart[p][2][kq8][colA] = pairsum(aA2);
        zpart[p][3][kq8][colA] = pairsum(aA3);
        zpart[p][0][kq8][colB] = pairsum(aB0);
        zpart[p][1][kq8][colB] = pairsum(aB1);
        zpart[p][2][kq8][colB] = pairsum(aB2);
        zpart[p][3][kq8][colB] = pairsum(aB3);
        __syncthreads();

        // latch step-t mask BEFORE prefetch overwrites mv
        const float mvc = mv;

        // ---- activation phase: all 16 warps, one (batch,gate) each ----
        {
            const int zc = ag * 32 + lane;
            float z = 0.f;
            #pragma unroll
            for (int q = 0; q < 8; q++)
                z += zpart[p][ab][q][zc];
            const float keep = 1.f - mvc;
            float uval = xv + keep * z;
            float uu   = (ag == 2) ? 2.f * uval : uval;
            float s    = sigf(uu);
            act_s[ag][ab][lane] = (ag == 2) ? 2.f * s - 1.f : s;
        }
        // prefetch next step's x/M while the bar drains
        if (t < TT - 1) {
            xv = g_xz[(size_t)(rowoff + (unsigned)t + 1u) * G4 + aj];
            mv = M[rowoff + (unsigned)t + 1u];
        }
        __syncthreads();   // act_s ready

        // ---- c-chain + exchange: warps 0-3 (batch = w) ----
        if (w < 4) {
            const float keep = 1.f - mvc;   // warp w has ag==0, ab==w
            float ig = act_s[0][w][lane];
            float fg = act_s[1][w][lane];
            float gg = act_s[2][w][lane];
            float og = act_s[3][w][lane];

            float c = fg * (keep * c_st) + ig * gg;
            c_st = c;
            float th = 2.f * sigf(2.f * c) - 1.f;
            float hh = og * th;

            if (t < TT - 1) {
                // sends FIRST (cluster-visible event), out STG after
                hstage[w][lane] = hh;
                __syncwarp();
                const int chunk = lane & 7;
                const uint32_t pr = (uint32_t)(lane >> 3);
                uint4 v = *(const uint4*)&hstage[w][chunk * 4];
                uint32_t laddr = hbase +
                    (uint32_t)(((pn * NB + w) * HH + rank * 32 + chunk * 4) * 4);
                uint32_t lmb = mbase + (uint32_t)(pn * 8);
                stasync_v4(laddr, lmb, pr,      v);
                stasync_v4(laddr, lmb, pr + 4u, v);
            }
            out[(size_t)(rowoff + (unsigned)t) * HH + rank * 32 + lane] = hh;
        }
    }
    cl_sync();   // don't exit while peers may still write our smem
}

// ---------------- launch ---------------------------------------------------
extern "C" void kernel_launch(void* const* d_in, const int* in_sizes, int n_in,
                              void* d_out, int out_size) {
    const float* obs     = (const float*)d_in[0];
    const float* S       = (const float*)d_in[1];
    const float* M       = (const float*)d_in[2];
    const float* W_embed = (const float*)d_in[3];
    const float* b_embed = (const float*)d_in[4];
    const float* kern    = (const float*)d_in[5];
    const float* rec     = (const float*)d_in[6];
    const float* bias    = (const float*)d_in[7];
    float* out = (float*)d_out;

    prep_kernel<<<65, 1024>>>(W_embed, b_embed, kern, bias);
    xz_kernel<<<4096, 256>>>(obs);
    rec_kernel<<<BB / NB * CLU, 512>>>(S, M, rec, out);
}